// round 14
// baseline (speedup 1.0000x reference)
#include <cuda_runtime.h>
#include <cuda.h>
#include <cuda_bf16.h>
#include <cstdint>
#include <cstddef>

#define HID 128
#define BM 64
#define TILE_BYTES 32768
#define GRID_MAIN 296          // 2 CTAs per SM
#define NTHREADS 128

// ---------------- device scratch ----------------
__device__ float g_B[HID * HID];                 // Wiv @ Wv
__device__ float g_u[HID];
__device__ __nv_bfloat16 g_Bf[16 * 8 * 2 * 32 * 2]; // 0.5*M^T bf16, fragment layout
__device__ float g_c[HID];
__device__ unsigned int g_tile_ctr;
__device__ unsigned int g_sync;                  // epoch barrier (monotonic)

__device__ __forceinline__ uint32_t smem_u32(const void* p) {
    uint32_t a;
    asm("{ .reg .u64 t; cvta.to.shared.u64 t, %1; cvt.u32.u64 %0, t; }" : "=r"(a) : "l"(p));
    return a;
}
__device__ __forceinline__ float warp_red(float p) {
    p += __shfl_xor_sync(0xffffffffu, p, 16);
    p += __shfl_xor_sync(0xffffffffu, p, 8);
    p += __shfl_xor_sync(0xffffffffu, p, 4);
    p += __shfl_xor_sync(0xffffffffu, p, 2);
    p += __shfl_xor_sync(0xffffffffu, p, 1);
    return p;
}
__device__ __forceinline__ uint32_t packbf(float lo, float hi) {
    uint32_t d;
    asm("cvt.rn.bf16x2.f32 %0, %1, %2;" : "=r"(d) : "f"(hi), "f"(lo));
    return d;
}
#define CPA16(dst, src) \
    asm volatile("cp.async.cg.shared.global [%0], [%1], 16;" :: "r"(dst), "l"(src))
#define CPA_WAIT_ALL() \
    asm volatile("cp.async.commit_group;\ncp.async.wait_group 0;" ::: "memory")

// ================= prep (single kernel, 64 blocks x 2 rows) ===============
// (verbatim from R12/R13 — proven correct)
__global__ __launch_bounds__(256) void prep(
    const float* __restrict__ Wo, const float* __restrict__ W_mo,
    const float* __restrict__ W_in, const float* __restrict__ Wv,
    const float* __restrict__ bv, const float* __restrict__ b_in,
    const float* __restrict__ b_mo, const float* __restrict__ bo)
{
    extern __shared__ float sm[];          // sW[16384] | sV[16384]
    float* sW = sm;
    float* sV = sm + 16384;
    __shared__ float sWo[2][HID], sWiv[2][HID], sAsh[2][HID], sw_own[2];

    const int b = blockIdx.x, t = threadIdx.x;
    const int r0 = b * 2;
    if (b == 0 && t == 0) g_tile_ctr = 0;

    const uint32_t sWa  = smem_u32(sW);
    const uint32_t sVa  = smem_u32(sV);
    const uint32_t sWoA = smem_u32(&sWo[0][0]);
    const uint32_t sWiA = smem_u32(&sWiv[0][0]);
    if (t < 64) {
        CPA16(sWoA + t * 16, Wo + r0 * HID + t * 4);
    } else if (t < 128) {
        const int i = t - 64;
        CPA16(sWiA + i * 16, W_in + (256 + r0) * HID + i * 4);
    }
    #pragma unroll
    for (int q = 0; q < 16; ++q) {
        const int i = q * 256 + t;
        CPA16(sWa + i * 16, W_mo + i * 4);
        CPA16(sVa + i * 16, Wv + i * 4);
    }
    CPA_WAIT_ALL();
    __syncthreads();

    const int wid = t >> 5, lane = t & 31;
    if (t < HID) {
        float a0 = 0.f, a1 = 0.f;
        #pragma unroll
        for (int j = 0; j < HID; ++j) {
            const float m = sW[j * HID + t];
            a0 += sWo[0][j] * m;
            a1 += sWo[1][j] * m;
        }
        sAsh[0][t] = a0;
        sAsh[1][t] = a1;
    } else {
        const int c = t - HID;
        float a0 = 0.f, a1 = 0.f;
        #pragma unroll
        for (int j = 0; j < HID; ++j) {
            const float m = sV[j * HID + c];
            a0 += sWiv[0][j] * m;
            a1 += sWiv[1][j] * m;
        }
        g_B[(r0 + 0) * HID + c] = a0;
        g_B[(r0 + 1) * HID + c] = a1;
    }
    if (wid < 2) {
        float p = 0.f;
        #pragma unroll
        for (int j = lane; j < HID; j += 32) p += sWiv[wid][j] * bv[j];
        p = warp_red(p);
        if (lane == 0) g_u[r0 + wid] = p + b_in[256 + r0 + wid];
    } else if (wid < 4) {
        const int rr = wid - 2;
        float p = 0.f;
        #pragma unroll
        for (int j = lane; j < HID; j += 32) p += sWo[rr][j] * b_mo[j];
        p = warp_red(p);
        if (lane == 0) sw_own[rr] = p + bo[r0 + rr];
    }
    __threadfence();
    __syncthreads();

    if (t == 0) {
        const unsigned v = atomicAdd(&g_sync, 1u);
        const unsigned target = ((v >> 6) + 1u) << 6;
        unsigned cur;
        do {
            asm volatile("ld.volatile.global.u32 %0, [%1];" : "=r"(cur) : "l"(&g_sync));
        } while (cur < target);
    }
    __syncthreads();

    #pragma unroll
    for (int q = 0; q < 16; ++q) {
        const int i = q * 256 + t;
        CPA16(sWa + i * 16, g_B + i * 4);
    }
    CPA_WAIT_ALL();
    __syncthreads();

    if (t < HID) {
        float m0 = 0.f, m1 = 0.f;
        #pragma unroll
        for (int j = 0; j < HID; ++j) {
            const float v = sW[j * HID + t];
            m0 += sAsh[0][j] * v;
            m1 += sAsh[1][j] * v;
        }
        const int i = t;
        const int ks = i >> 4, r = i & 15;
        const int regi = (r >> 3) & 1, half = r & 1;
        #pragma unroll
        for (int rr = 0; rr < 2; ++rr) {
            const int o = r0 + rr;
            const int nt = o >> 3;
            const int lane2 = ((o & 7) << 2) | ((r & 7) >> 1);
            const int idx = ((((nt * 8 + ks) * 2 + regi) * 32) + lane2) * 2 + half;
            g_Bf[idx] = __float2bfloat16(0.5f * (rr ? m1 : m0));
        }
    }
    if (wid < 2) {
        float p = 0.f;
        #pragma unroll
        for (int j = lane; j < HID; j += 32) p += sAsh[wid][j] * g_u[j];
        p = warp_red(p);
        if (lane == 0) g_c[r0 + wid] = 0.5f * (p + sw_own[wid]);
    }
}

// ================= main: 2 CTAs/SM x 128 threads, STG epilogue ============
// per-CTA smem: XS0..2 @0/32768/65536 (32KB fp32 SW128), XB @98304 (16KB),
//               mbar[3] @114688, sTick[3] @114712; total 114752
#define OFF_XB   98304u
#define OFF_MBAR 114688u
#define OFF_TICK 114712u
#define SMEM_TOTAL 114752

#define MBAR_INIT(a, c) \
    asm volatile("mbarrier.init.shared.b64 [%0], %1;" :: "r"(a), "r"(c) : "memory")
#define MBAR_EXPECT(a, b) \
    asm volatile("mbarrier.arrive.expect_tx.shared.b64 _, [%0], %1;" :: "r"(a), "r"(b) : "memory")
#define MBAR_WAIT(mbar, par) do {                                             \
    uint32_t _m = (mbar); uint32_t _p = (par); uint32_t _d;                   \
    asm volatile("{\n\t.reg .pred p;\n\t"                                     \
        "mbarrier.try_wait.parity.acquire.cta.shared::cta.b64 p, [%1], %2;\n\t" \
        "selp.b32 %0, 1, 0, p;\n\t}"                                          \
        : "=r"(_d) : "r"(_m), "r"(_p) : "memory");                            \
    if (!_d) {                                                                \
        asm volatile("{\n\t.reg .pred P1;\n\t"                                \
            "W_%=:\n\t"                                                       \
            "mbarrier.try_wait.parity.acquire.cta.shared::cta.b64 P1, [%0], %1, 0x989680;\n\t" \
            "@P1 bra.uni D_%=;\n\t"                                           \
            "bra.uni W_%=;\n\t"                                               \
            "D_%=:\n\t}" :: "r"(_m), "r"(_p) : "memory");                     \
    }                                                                         \
} while (0)

#define TMA_LOAD2D(dst, map, x, y, mb) \
    asm volatile("cp.async.bulk.tensor.2d.shared::cta.global.tile.mbarrier::complete_tx::bytes " \
                 "[%0], [%1, {%2, %3}], [%4];" \
                 :: "r"(dst), "l"(map), "r"(x), "r"(y), "r"(mb) : "memory")

__global__ __launch_bounds__(NTHREADS, 2) void fused_main(
    const __grid_constant__ CUtensorMap tmX,
    float* __restrict__ Y,
    int ntiles, int E)
{
    extern __shared__ __align__(1024) unsigned char smem_raw[];
    const uint32_t sb = smem_u32(smem_raw);
    const int tid  = threadIdx.x;
    const int lane = tid & 31;
    const int wn = tid >> 5;                 // 1(m) x 4(n) warp grid
    const uint32_t xs_a[3] = { sb, sb + 32768u, sb + 65536u };
    const uint32_t xb = sb + OFF_XB;
    unsigned* sTick = reinterpret_cast<unsigned*>(smem_raw + OFF_TICK);

    // ---- B fragments in registers ----
    uint32_t breg[4][8][2];
    {
        const uint32_t* bp = reinterpret_cast<const uint32_t*>(g_Bf);
        #pragma unroll
        for (int nt = 0; nt < 4; ++nt)
            #pragma unroll
            for (int ks = 0; ks < 8; ++ks)
                #pragma unroll
                for (int ri = 0; ri < 2; ++ri)
                    breg[nt][ks][ri] =
                        bp[(((wn * 4 + nt) * 8 + ks) * 2 + ri) * 32 + lane];
    }
    float cv[4][2];
    #pragma unroll
    for (int nt = 0; nt < 4; ++nt) {
        const int col = wn * 32 + nt * 8 + 2 * (lane & 3);
        cv[nt][0] = g_c[col];
        cv[nt][1] = g_c[col + 1];
    }

    if (tid == 0) {
        #pragma unroll
        for (int st = 0; st < 3; ++st) MBAR_INIT(sb + OFF_MBAR + 8 * st, 1);
    }
    __syncthreads();

    // prologue: 3 tickets, 3 loads
    if (tid == 0) {
        #pragma unroll
        for (int st = 0; st < 3; ++st) {
            const unsigned c = atomicAdd(&g_tile_ctr, 1u);
            sTick[st] = c;
            if (c < (unsigned)ntiles) {
                MBAR_EXPECT(sb + OFF_MBAR + 8 * st, TILE_BYTES);
                #pragma unroll
                for (int ac = 0; ac < 4; ++ac)
                    TMA_LOAD2D(xs_a[st] + ac * 8192, &tmX, ac * 32, (int)c * BM,
                               sb + OFF_MBAR + 8 * st);
            }
        }
    }
    __syncthreads();

    // per-thread constants
    const int crow = tid >> 1, ch = tid & 1;   // convert: 64 rows x 2 threads
    const uint32_t cr7 = (uint32_t)(crow & 7);
    const int rsub = lane & 15;
    const uint32_t lr7 = (uint32_t)(rsub & 7);
    const int khalf = lane >> 4;
    const uint32_t er7a = (uint32_t)(lane >> 2);
    const uint32_t einner = (uint32_t)(lane & 1) * 8;
    const uint32_t eq16b = (uint32_t)((lane & 3) >> 1);
    const int ecol = wn * 32 + (lane & 3) * 2; // base global column (nt adds 8*nt)

    unsigned ph = 0;

    for (int i = 0; ; ++i) {
        const int p = i % 3;
        const unsigned q = sTick[p];
        if (q >= (unsigned)ntiles) break;

        MBAR_WAIT(sb + OFF_MBAR + 8 * p, (ph >> p) & 1);
        ph ^= (1u << p);

        // ---- convert fp32 XS[p] -> bf16 XB ----
        {
            const uint32_t rxs = xs_a[p] + (uint32_t)crow * 128;
            const uint32_t rxb = xb + (uint32_t)crow * 256;
            #pragma unroll
            for (int j = 0; j < 8; ++j) {
                const int cj = ch * 8 + j;
                const uint32_t c32 = (uint32_t)(cj >> 2) * 8192;
                const uint32_t q0 = (uint32_t)((cj & 3) * 2);
                const uint32_t a0 = rxs + c32 + ((q0 ^ cr7) << 4);
                const uint32_t a1 = rxs + c32 + (((q0 + 1) ^ cr7) << 4);
                float x0, x1, x2, x3, y0, y1, y2, y3;
                asm volatile("ld.shared.v4.f32 {%0,%1,%2,%3}, [%4];"
                             : "=f"(x0), "=f"(x1), "=f"(x2), "=f"(x3) : "r"(a0));
                asm volatile("ld.shared.v4.f32 {%0,%1,%2,%3}, [%4];"
                             : "=f"(y0), "=f"(y1), "=f"(y2), "=f"(y3) : "r"(a1));
                const uint32_t p0 = packbf(x0, x1), p1 = packbf(x2, x3);
                const uint32_t p2 = packbf(y0, y1), p3 = packbf(y2, y3);
                const uint32_t ab = rxb + (((uint32_t)cj ^ cr7) << 4);
                asm volatile("st.shared.v4.b32 [%0], {%1,%2,%3,%4};"
                             :: "r"(ab), "r"(p0), "r"(p1), "r"(p2), "r"(p3) : "memory");
            }
        }
        __syncthreads();   // XB ready

        // ---- mma from XB: warp tile m64 x n32 ----
        float acc[4][4][4];
        #pragma unroll
        for (int mt = 0; mt < 4; ++mt)
            #pragma unroll
            for (int nt = 0; nt < 4; ++nt)
                #pragma unroll
                for (int qq = 0; qq < 4; ++qq) acc[mt][nt][qq] = 0.f;

        #pragma unroll
        for (int ks = 0; ks < 8; ++ks) {
            uint32_t a[4][4];
            const uint32_t chunk = (uint32_t)(2 * ks + khalf);
            const uint32_t csw = (chunk ^ lr7) << 4;
            #pragma unroll
            for (int mt = 0; mt < 4; ++mt) {
                const uint32_t addr =
                    xb + (uint32_t)(mt * 16 + rsub) * 256 + csw;
                asm volatile("ldmatrix.sync.aligned.m8n8.x4.shared.b16 {%0,%1,%2,%3}, [%4];"
                             : "=r"(a[mt][0]), "=r"(a[mt][1]), "=r"(a[mt][2]), "=r"(a[mt][3])
                             : "r"(addr));
            }
            #pragma unroll
            for (int mt = 0; mt < 4; ++mt)
                #pragma unroll
                for (int nt = 0; nt < 4; ++nt) {
                    asm volatile(
                        "mma.sync.aligned.m16n8k16.row.col.f32.bf16.bf16.f32 "
                        "{%0,%1,%2,%3}, {%4,%5,%6,%7}, {%8,%9}, {%0,%1,%2,%3};"
                        : "+f"(acc[mt][nt][0]), "+f"(acc[mt][nt][1]),
                          "+f"(acc[mt][nt][2]), "+f"(acc[mt][nt][3])
                        : "r"(a[mt][0]), "r"(a[mt][1]), "r"(a[mt][2]), "r"(a[mt][3]),
                          "r"(breg[nt][ks][0]), "r"(breg[nt][ks][1]));
                }
        }

        // ---- epilogue: Y = X(smem) + acc + c -> STG directly ----
        {
            const uint32_t xsn = xs_a[p] + (uint32_t)wn * 8192;
            const int rowbase = (int)q * BM;
            #pragma unroll
            for (int mt = 0; mt < 4; ++mt) {
                const uint32_t rA = (uint32_t)(mt * 16) + (uint32_t)(lane >> 2);
                const uint32_t rB = rA + 8;
                const uint32_t baseA = xsn + rA * 128;
                const uint32_t baseB = xsn + rB * 128;
                const int gA = rowbase + (int)rA;
                const int gB = rowbase + (int)rB;
                #pragma unroll
                for (int nt = 0; nt < 4; ++nt) {
                    const uint32_t q16 = (uint32_t)(nt * 2) + eq16b;
                    const uint32_t swo = ((q16 ^ er7a) << 4) + einner;
                    const int col = ecol + nt * 8;
                    float f0, f1;
                    if (gA < E) {
                        asm volatile("ld.shared.v2.f32 {%0,%1}, [%2];"
                                     : "=f"(f0), "=f"(f1) : "r"(baseA + swo));
                        float2 o;
                        o.x = f0 + acc[mt][nt][0] + cv[nt][0];
                        o.y = f1 + acc[mt][nt][1] + cv[nt][1];
                        *reinterpret_cast<float2*>(Y + (size_t)gA * HID + col) = o;
                    }
                    if (gB < E) {
                        asm volatile("ld.shared.v2.f32 {%0,%1}, [%2];"
                                     : "=f"(f0), "=f"(f1) : "r"(baseB + swo));
                        float2 o;
                        o.x = f0 + acc[mt][nt][2] + cv[nt][0];
                        o.y = f1 + acc[mt][nt][3] + cv[nt][1];
                        *reinterpret_cast<float2*>(Y + (size_t)gB * HID + col) = o;
                    }
                }
            }
        }
        __syncthreads();   // all reads of XS[p] and XB done

        // ---- tid0: immediately reload stage p with a new ticket ----
        if (tid == 0) {
            const unsigned nn = atomicAdd(&g_tile_ctr, 1u);
            sTick[p] = nn;
            if (nn < (unsigned)ntiles) {
                MBAR_EXPECT(sb + OFF_MBAR + 8 * p, TILE_BYTES);
                #pragma unroll
                for (int ac = 0; ac < 4; ++ac)
                    TMA_LOAD2D(xs_a[p] + ac * 8192, &tmX, ac * 32, (int)nn * BM,
                               sb + OFF_MBAR + 8 * p);
            }
        }
    }
}

// ================= host ====================================================
typedef CUresult (*PFN_encodeTiled)(
    CUtensorMap*, CUtensorMapDataType, cuuint32_t, void*,
    const cuuint64_t*, const cuuint64_t*, const cuuint32_t*, const cuuint32_t*,
    CUtensorMapInterleave, CUtensorMapSwizzle, CUtensorMapL2promotion,
    CUtensorMapFloatOOBfill);

extern "C" void kernel_launch(void* const* d_in, const int* in_sizes, int n_in,
                              void* d_out, int out_size)
{
    const float* X    = (const float*)d_in[0];
    const float* Wv   = (const float*)d_in[7];
    const float* bv   = (const float*)d_in[8];
    const float* W_in = (const float*)d_in[9];
    const float* b_in = (const float*)d_in[10];
    const float* W_mo = (const float*)d_in[11];
    const float* b_mo = (const float*)d_in[12];
    const float* Wo   = (const float*)d_in[13];
    const float* bo   = (const float*)d_in[14];
    float* Y = (float*)d_out;

    const int E = in_sizes[0] / HID;
    const int ntiles = (E + BM - 1) / BM;

    cudaFuncSetAttribute(prep, cudaFuncAttributeMaxDynamicSharedMemorySize, 131072);
    prep<<<64, 256, 131072>>>(Wo, W_mo, W_in, Wv, bv, b_in, b_mo, bo);

    void* pfn = nullptr;
    cudaDriverEntryPointQueryResult qr;
    cudaGetDriverEntryPoint("cuTensorMapEncodeTiled", &pfn, cudaEnableDefault, &qr);
    PFN_encodeTiled encode = (PFN_encodeTiled)pfn;

    CUtensorMap tmX;
    cuuint64_t dims[2] = { (cuuint64_t)HID, (cuuint64_t)E };
    cuuint64_t str[1]  = { (cuuint64_t)HID * 4 };
    cuuint32_t box[2]  = { 32, 64 };
    cuuint32_t es[2]   = { 1, 1 };
    encode(&tmX, CU_TENSOR_MAP_DATA_TYPE_FLOAT32, 2, (void*)X,
           dims, str, box, es, CU_TENSOR_MAP_INTERLEAVE_NONE,
           CU_TENSOR_MAP_SWIZZLE_128B, CU_TENSOR_MAP_L2_PROMOTION_L2_128B,
           CU_TENSOR_MAP_FLOAT_OOB_FILL_NONE);

    cudaFuncSetAttribute(fused_main, cudaFuncAttributeMaxDynamicSharedMemorySize, SMEM_TOTAL);
    fused_main<<<GRID_MAIN, NTHREADS, SMEM_TOTAL>>>(tmX, Y, ntiles, E);
}

// round 15
// speedup vs baseline: 1.1836x; 1.1836x over previous
#include <cuda_runtime.h>
#include <cuda.h>
#include <cuda_bf16.h>
#include <cstdint>
#include <cstddef>

#define HID 128
#define BM 64
#define TILE_BYTES 32768
#define GRID_MAIN 296          // 2 CTAs per SM
#define NTHREADS 128

// ---------------- device scratch ----------------
__device__ float g_B[HID * HID];                 // Wiv @ Wv
__device__ float g_u[HID];
__device__ __nv_bfloat16 g_Bf[16 * 8 * 2 * 32 * 2]; // 0.5*M^T bf16, fragment layout
__device__ float g_c[HID];
__device__ unsigned int g_tile_ctr;
__device__ unsigned int g_sync;                  // epoch barrier (monotonic)

__device__ __forceinline__ uint32_t smem_u32(const void* p) {
    uint32_t a;
    asm("{ .reg .u64 t; cvta.to.shared.u64 t, %1; cvt.u32.u64 %0, t; }" : "=r"(a) : "l"(p));
    return a;
}
__device__ __forceinline__ float warp_red(float p) {
    p += __shfl_xor_sync(0xffffffffu, p, 16);
    p += __shfl_xor_sync(0xffffffffu, p, 8);
    p += __shfl_xor_sync(0xffffffffu, p, 4);
    p += __shfl_xor_sync(0xffffffffu, p, 2);
    p += __shfl_xor_sync(0xffffffffu, p, 1);
    return p;
}
__device__ __forceinline__ uint32_t packbf(float lo, float hi) {
    uint32_t d;
    asm("cvt.rn.bf16x2.f32 %0, %1, %2;" : "=r"(d) : "f"(hi), "f"(lo));
    return d;
}
#define CPA16(dst, src) \
    asm volatile("cp.async.cg.shared.global [%0], [%1], 16;" :: "r"(dst), "l"(src))
#define CPA_WAIT_ALL() \
    asm volatile("cp.async.commit_group;\ncp.async.wait_group 0;" ::: "memory")

// ================= prep (single kernel, 64 blocks x 2 rows) ===============
// (verbatim from R12/R13 — proven correct)
__global__ __launch_bounds__(256) void prep(
    const float* __restrict__ Wo, const float* __restrict__ W_mo,
    const float* __restrict__ W_in, const float* __restrict__ Wv,
    const float* __restrict__ bv, const float* __restrict__ b_in,
    const float* __restrict__ b_mo, const float* __restrict__ bo)
{
    extern __shared__ float sm[];          // sW[16384] | sV[16384]
    float* sW = sm;
    float* sV = sm + 16384;
    __shared__ float sWo[2][HID], sWiv[2][HID], sAsh[2][HID], sw_own[2];

    const int b = blockIdx.x, t = threadIdx.x;
    const int r0 = b * 2;
    if (b == 0 && t == 0) g_tile_ctr = 0;

    const uint32_t sWa  = smem_u32(sW);
    const uint32_t sVa  = smem_u32(sV);
    const uint32_t sWoA = smem_u32(&sWo[0][0]);
    const uint32_t sWiA = smem_u32(&sWiv[0][0]);
    if (t < 64) {
        CPA16(sWoA + t * 16, Wo + r0 * HID + t * 4);
    } else if (t < 128) {
        const int i = t - 64;
        CPA16(sWiA + i * 16, W_in + (256 + r0) * HID + i * 4);
    }
    #pragma unroll
    for (int q = 0; q < 16; ++q) {
        const int i = q * 256 + t;
        CPA16(sWa + i * 16, W_mo + i * 4);
        CPA16(sVa + i * 16, Wv + i * 4);
    }
    CPA_WAIT_ALL();
    __syncthreads();

    const int wid = t >> 5, lane = t & 31;
    if (t < HID) {
        float a0 = 0.f, a1 = 0.f;
        #pragma unroll
        for (int j = 0; j < HID; ++j) {
            const float m = sW[j * HID + t];
            a0 += sWo[0][j] * m;
            a1 += sWo[1][j] * m;
        }
        sAsh[0][t] = a0;
        sAsh[1][t] = a1;
    } else {
        const int c = t - HID;
        float a0 = 0.f, a1 = 0.f;
        #pragma unroll
        for (int j = 0; j < HID; ++j) {
            const float m = sV[j * HID + c];
            a0 += sWiv[0][j] * m;
            a1 += sWiv[1][j] * m;
        }
        g_B[(r0 + 0) * HID + c] = a0;
        g_B[(r0 + 1) * HID + c] = a1;
    }
    if (wid < 2) {
        float p = 0.f;
        #pragma unroll
        for (int j = lane; j < HID; j += 32) p += sWiv[wid][j] * bv[j];
        p = warp_red(p);
        if (lane == 0) g_u[r0 + wid] = p + b_in[256 + r0 + wid];
    } else if (wid < 4) {
        const int rr = wid - 2;
        float p = 0.f;
        #pragma unroll
        for (int j = lane; j < HID; j += 32) p += sWo[rr][j] * b_mo[j];
        p = warp_red(p);
        if (lane == 0) sw_own[rr] = p + bo[r0 + rr];
    }
    __threadfence();
    __syncthreads();

    if (t == 0) {
        const unsigned v = atomicAdd(&g_sync, 1u);
        const unsigned target = ((v >> 6) + 1u) << 6;
        unsigned cur;
        do {
            asm volatile("ld.volatile.global.u32 %0, [%1];" : "=r"(cur) : "l"(&g_sync));
        } while (cur < target);
    }
    __syncthreads();

    #pragma unroll
    for (int q = 0; q < 16; ++q) {
        const int i = q * 256 + t;
        CPA16(sWa + i * 16, g_B + i * 4);
    }
    CPA_WAIT_ALL();
    __syncthreads();

    if (t < HID) {
        float m0 = 0.f, m1 = 0.f;
        #pragma unroll
        for (int j = 0; j < HID; ++j) {
            const float v = sW[j * HID + t];
            m0 += sAsh[0][j] * v;
            m1 += sAsh[1][j] * v;
        }
        const int i = t;
        const int ks = i >> 4, r = i & 15;
        const int regi = (r >> 3) & 1, half = r & 1;
        #pragma unroll
        for (int rr = 0; rr < 2; ++rr) {
            const int o = r0 + rr;
            const int nt = o >> 3;
            const int lane2 = ((o & 7) << 2) | ((r & 7) >> 1);
            const int idx = ((((nt * 8 + ks) * 2 + regi) * 32) + lane2) * 2 + half;
            g_Bf[idx] = __float2bfloat16(0.5f * (rr ? m1 : m0));
        }
    }
    if (wid < 2) {
        float p = 0.f;
        #pragma unroll
        for (int j = lane; j < HID; j += 32) p += sAsh[wid][j] * g_u[j];
        p = warp_red(p);
        if (lane == 0) g_c[r0 + wid] = 0.5f * (p + sw_own[wid]);
    }
}

// ================= main: 2 CTAs/SM x 128 threads, fused acc-init ==========
// per-CTA smem: XS0..2 @0/32768/65536 (32KB fp32 SW128), XB @98304 (16KB),
//               mbar[3] @114688, sTick[3] @114712; total 114752
#define OFF_XB   98304u
#define OFF_MBAR 114688u
#define OFF_TICK 114712u
#define SMEM_TOTAL 114752

#define MBAR_INIT(a, c) \
    asm volatile("mbarrier.init.shared.b64 [%0], %1;" :: "r"(a), "r"(c) : "memory")
#define MBAR_EXPECT(a, b) \
    asm volatile("mbarrier.arrive.expect_tx.shared.b64 _, [%0], %1;" :: "r"(a), "r"(b) : "memory")
#define MBAR_WAIT(mbar, par) do {                                             \
    uint32_t _m = (mbar); uint32_t _p = (par); uint32_t _d;                   \
    asm volatile("{\n\t.reg .pred p;\n\t"                                     \
        "mbarrier.try_wait.parity.acquire.cta.shared::cta.b64 p, [%1], %2;\n\t" \
        "selp.b32 %0, 1, 0, p;\n\t}"                                          \
        : "=r"(_d) : "r"(_m), "r"(_p) : "memory");                            \
    if (!_d) {                                                                \
        asm volatile("{\n\t.reg .pred P1;\n\t"                                \
            "W_%=:\n\t"                                                       \
            "mbarrier.try_wait.parity.acquire.cta.shared::cta.b64 P1, [%0], %1, 0x989680;\n\t" \
            "@P1 bra.uni D_%=;\n\t"                                           \
            "bra.uni W_%=;\n\t"                                               \
            "D_%=:\n\t}" :: "r"(_m), "r"(_p) : "memory");                     \
    }                                                                         \
} while (0)

#define TMA_LOAD2D(dst, map, x, y, mb) \
    asm volatile("cp.async.bulk.tensor.2d.shared::cta.global.tile.mbarrier::complete_tx::bytes " \
                 "[%0], [%1, {%2, %3}], [%4];" \
                 :: "r"(dst), "l"(map), "r"(x), "r"(y), "r"(mb) : "memory")
#define TMA_STORE2D(map, x, y, src) \
    asm volatile("cp.async.bulk.tensor.2d.global.shared::cta.tile.bulk_group " \
                 "[%0, {%1, %2}], [%3];" \
                 :: "l"(map), "r"(x), "r"(y), "r"(src) : "memory")
#define FENCE_ASYNC() asm volatile("fence.proxy.async.shared::cta;" ::: "memory")

__global__ __launch_bounds__(NTHREADS, 2) void fused_main(
    const __grid_constant__ CUtensorMap tmX,
    const __grid_constant__ CUtensorMap tmY,
    int ntiles)
{
    extern __shared__ __align__(1024) unsigned char smem_raw[];
    const uint32_t sb = smem_u32(smem_raw);
    const int tid  = threadIdx.x;
    const int lane = tid & 31;
    const int wn = tid >> 5;                 // 1(m) x 4(n) warp grid
    const uint32_t xs_a[3] = { sb, sb + 32768u, sb + 65536u };
    const uint32_t xb = sb + OFF_XB;
    unsigned* sTick = reinterpret_cast<unsigned*>(smem_raw + OFF_TICK);

    // ---- B fragments in registers ----
    uint32_t breg[4][8][2];
    {
        const uint32_t* bp = reinterpret_cast<const uint32_t*>(g_Bf);
        #pragma unroll
        for (int nt = 0; nt < 4; ++nt)
            #pragma unroll
            for (int ks = 0; ks < 8; ++ks)
                #pragma unroll
                for (int ri = 0; ri < 2; ++ri)
                    breg[nt][ks][ri] =
                        bp[(((wn * 4 + nt) * 8 + ks) * 2 + ri) * 32 + lane];
    }
    float cv[4][2];
    #pragma unroll
    for (int nt = 0; nt < 4; ++nt) {
        const int col = wn * 32 + nt * 8 + 2 * (lane & 3);
        cv[nt][0] = g_c[col];
        cv[nt][1] = g_c[col + 1];
    }

    if (tid == 0) {
        #pragma unroll
        for (int st = 0; st < 3; ++st) MBAR_INIT(sb + OFF_MBAR + 8 * st, 1);
    }
    __syncthreads();

    // prologue: 3 tickets, 3 loads
    if (tid == 0) {
        #pragma unroll
        for (int st = 0; st < 3; ++st) {
            const unsigned c = atomicAdd(&g_tile_ctr, 1u);
            sTick[st] = c;
            if (c < (unsigned)ntiles) {
                MBAR_EXPECT(sb + OFF_MBAR + 8 * st, TILE_BYTES);
                #pragma unroll
                for (int ac = 0; ac < 4; ++ac)
                    TMA_LOAD2D(xs_a[st] + ac * 8192, &tmX, ac * 32, (int)c * BM,
                               sb + OFF_MBAR + 8 * st);
            }
        }
    }
    __syncthreads();

    // per-thread constants
    const int rsub = lane & 15;
    const uint32_t lr7 = (uint32_t)(rsub & 7);
    const int khalf = lane >> 4;
    // acc-ownership constants: rows mt*16 + (lane>>2) (+8), cols nt*8 + 2*(lane&3)
    const uint32_t rquo = (uint32_t)(lane >> 2);
    const uint32_t c32b = (uint32_t)(2 * (lane & 3));   // base within-block col

    unsigned ph = 0;
    int pend_stage = -1;
    unsigned pend_tick = 0;

    for (int i = 0; ; ++i) {
        const int p = i % 3;
        const unsigned q = sTick[p];
        if (q >= (unsigned)ntiles) break;

        MBAR_WAIT(sb + OFF_MBAR + 8 * p, (ph >> p) & 1);
        ph ^= (1u << p);

        float acc[4][4][4];

        // ---- fused: read X (acc ownership pattern), init acc = X + c,
        //      pack bf16 -> XB (swizzled) ----
        {
            const uint32_t xsn = xs_a[p] + (uint32_t)wn * 8192;
            #pragma unroll
            for (int mt = 0; mt < 4; ++mt) {
                const uint32_t rA = (uint32_t)(mt * 16) + rquo;
                const uint32_t rB = rA + 8;
                #pragma unroll
                for (int nt = 0; nt < 4; ++nt) {
                    const uint32_t c32 = (uint32_t)(nt * 8) + c32b;  // within 32-col block
                    const uint32_t cb = c32 * 4;
                    const uint32_t q16 = cb >> 4, inner = cb & 15;
                    const uint32_t aA = xsn + rA * 128 + ((q16 ^ (rA & 7)) << 4) + inner;
                    const uint32_t aB = xsn + rB * 128 + ((q16 ^ (rB & 7)) << 4) + inner;
                    float x0, x1, y0, y1;
                    asm volatile("ld.shared.v2.f32 {%0,%1}, [%2];"
                                 : "=f"(x0), "=f"(x1) : "r"(aA));
                    asm volatile("ld.shared.v2.f32 {%0,%1}, [%2];"
                                 : "=f"(y0), "=f"(y1) : "r"(aB));
                    acc[mt][nt][0] = x0 + cv[nt][0];
                    acc[mt][nt][1] = x1 + cv[nt][1];
                    acc[mt][nt][2] = y0 + cv[nt][0];
                    acc[mt][nt][3] = y1 + cv[nt][1];
                    // XB: global col = wn*32 + c32; byte = 2*col in 256B row
                    const uint32_t colb = (uint32_t)(wn * 64) + c32 * 2;
                    const uint32_t qx = colb >> 4, innx = colb & 15;
                    const uint32_t bA = xb + rA * 256 + ((qx ^ (rA & 7)) << 4) + innx;
                    const uint32_t bB = xb + rB * 256 + ((qx ^ (rB & 7)) << 4) + innx;
                    asm volatile("st.shared.b32 [%0], %1;"
                                 :: "r"(bA), "r"(packbf(x0, x1)) : "memory");
                    asm volatile("st.shared.b32 [%0], %1;"
                                 :: "r"(bB), "r"(packbf(y0, y1)) : "memory");
                }
            }
        }
        __syncthreads();   // XB ready

        // ---- mma from XB: warp tile m64 x n32, acc pre-initialized ----
        #pragma unroll
        for (int ks = 0; ks < 8; ++ks) {
            uint32_t a[4][4];
            const uint32_t chunk = (uint32_t)(2 * ks + khalf);
            const uint32_t csw = (chunk ^ lr7) << 4;
            #pragma unroll
            for (int mt = 0; mt < 4; ++mt) {
                const uint32_t addr =
                    xb + (uint32_t)(mt * 16 + rsub) * 256 + csw;
                asm volatile("ldmatrix.sync.aligned.m8n8.x4.shared.b16 {%0,%1,%2,%3}, [%4];"
                             : "=r"(a[mt][0]), "=r"(a[mt][1]), "=r"(a[mt][2]), "=r"(a[mt][3])
                             : "r"(addr));
            }
            #pragma unroll
            for (int mt = 0; mt < 4; ++mt)
                #pragma unroll
                for (int nt = 0; nt < 4; ++nt) {
                    asm volatile(
                        "mma.sync.aligned.m16n8k16.row.col.f32.bf16.bf16.f32 "
                        "{%0,%1,%2,%3}, {%4,%5,%6,%7}, {%8,%9}, {%0,%1,%2,%3};"
                        : "+f"(acc[mt][nt][0]), "+f"(acc[mt][nt][1]),
                          "+f"(acc[mt][nt][2]), "+f"(acc[mt][nt][3])
                        : "r"(a[mt][0]), "r"(a[mt][1]), "r"(a[mt][2]), "r"(a[mt][3]),
                          "r"(breg[nt][ks][0]), "r"(breg[nt][ks][1]));
                }
        }

        // ---- epilogue: pure STS of acc into XS[p] (residual+bias already in) ----
        {
            const uint32_t xsn = xs_a[p] + (uint32_t)wn * 8192;
            #pragma unroll
            for (int mt = 0; mt < 4; ++mt) {
                const uint32_t rA = (uint32_t)(mt * 16) + rquo;
                const uint32_t rB = rA + 8;
                #pragma unroll
                for (int nt = 0; nt < 4; ++nt) {
                    const uint32_t c32 = (uint32_t)(nt * 8) + c32b;
                    const uint32_t cb = c32 * 4;
                    const uint32_t q16 = cb >> 4, inner = cb & 15;
                    const uint32_t aA = xsn + rA * 128 + ((q16 ^ (rA & 7)) << 4) + inner;
                    const uint32_t aB = xsn + rB * 128 + ((q16 ^ (rB & 7)) << 4) + inner;
                    asm volatile("st.shared.v2.f32 [%0], {%1,%2};"
                                 :: "r"(aA), "f"(acc[mt][nt][0]), "f"(acc[mt][nt][1]) : "memory");
                    asm volatile("st.shared.v2.f32 [%0], {%1,%2};"
                                 :: "r"(aB), "f"(acc[mt][nt][2]), "f"(acc[mt][nt][3]) : "memory");
                }
            }
        }
        FENCE_ASYNC();
        __syncthreads();

        // ---- tid0: deferred reload, store tile q, new ticket (R13 scheme) ----
        if (tid == 0) {
            if (pend_stage >= 0) {
                asm volatile("cp.async.bulk.wait_group.read 0;" ::: "memory");
                if (pend_tick < (unsigned)ntiles) {
                    MBAR_EXPECT(sb + OFF_MBAR + 8 * pend_stage, TILE_BYTES);
                    #pragma unroll
                    for (int ac = 0; ac < 4; ++ac)
                        TMA_LOAD2D(xs_a[pend_stage] + ac * 8192, &tmX,
                                   ac * 32, (int)pend_tick * BM,
                                   sb + OFF_MBAR + 8 * pend_stage);
                }
            }
            #pragma unroll
            for (int ac = 0; ac < 4; ++ac)
                TMA_STORE2D(&tmY, ac * 32, (int)q * BM, xs_a[p] + ac * 8192);
            asm volatile("cp.async.bulk.commit_group;" ::: "memory");
            const unsigned nn = atomicAdd(&g_tile_ctr, 1u);
            sTick[p] = nn;
            pend_tick = nn;
        }
        pend_stage = p;
    }

    if (tid == 0)
        asm volatile("cp.async.bulk.wait_group 0;" ::: "memory");
}

// ================= host ====================================================
typedef CUresult (*PFN_encodeTiled)(
    CUtensorMap*, CUtensorMapDataType, cuuint32_t, void*,
    const cuuint64_t*, const cuuint64_t*, const cuuint32_t*, const cuuint32_t*,
    CUtensorMapInterleave, CUtensorMapSwizzle, CUtensorMapL2promotion,
    CUtensorMapFloatOOBfill);

extern "C" void kernel_launch(void* const* d_in, const int* in_sizes, int n_in,
                              void* d_out, int out_size)
{
    const float* X    = (const float*)d_in[0];
    const float* Wv   = (const float*)d_in[7];
    const float* bv   = (const float*)d_in[8];
    const float* W_in = (const float*)d_in[9];
    const float* b_in = (const float*)d_in[10];
    const float* W_mo = (const float*)d_in[11];
    const float* b_mo = (const float*)d_in[12];
    const float* Wo   = (const float*)d_in[13];
    const float* bo   = (const float*)d_in[14];
    float* Y = (float*)d_out;

    const int E = in_sizes[0] / HID;
    const int ntiles = (E + BM - 1) / BM;

    cudaFuncSetAttribute(prep, cudaFuncAttributeMaxDynamicSharedMemorySize, 131072);
    prep<<<64, 256, 131072>>>(Wo, W_mo, W_in, Wv, bv, b_in, b_mo, bo);

    void* pfn = nullptr;
    cudaDriverEntryPointQueryResult qr;
    cudaGetDriverEntryPoint("cuTensorMapEncodeTiled", &pfn, cudaEnableDefault, &qr);
    PFN_encodeTiled encode = (PFN_encodeTiled)pfn;

    CUtensorMap tmX, tmY;
    cuuint64_t dims[2] = { (cuuint64_t)HID, (cuuint64_t)E };
    cuuint64_t str[1]  = { (cuuint64_t)HID * 4 };
    cuuint32_t box[2]  = { 32, 64 };
    cuuint32_t es[2]   = { 1, 1 };
    encode(&tmX, CU_TENSOR_MAP_DATA_TYPE_FLOAT32, 2, (void*)X,
           dims, str, box, es, CU_TENSOR_MAP_INTERLEAVE_NONE,
           CU_TENSOR_MAP_SWIZZLE_128B, CU_TENSOR_MAP_L2_PROMOTION_L2_128B,
           CU_TENSOR_MAP_FLOAT_OOB_FILL_NONE);
    encode(&tmY, CU_TENSOR_MAP_DATA_TYPE_FLOAT32, 2, (void*)Y,
           dims, str, box, es, CU_TENSOR_MAP_INTERLEAVE_NONE,
           CU_TENSOR_MAP_SWIZZLE_128B, CU_TENSOR_MAP_L2_PROMOTION_L2_128B,
           CU_TENSOR_MAP_FLOAT_OOB_FILL_NONE);

    cudaFuncSetAttribute(fused_main, cudaFuncAttributeMaxDynamicSharedMemorySize, SMEM_TOTAL);
    fused_main<<<GRID_MAIN, NTHREADS, SMEM_TOTAL>>>(tmX, tmY, ntiles);
}

// round 16
// speedup vs baseline: 1.2229x; 1.0332x over previous
#include <cuda_runtime.h>
#include <cuda.h>
#include <cuda_bf16.h>
#include <cstdint>
#include <cstddef>

#define HID 128
#define BM 64
#define TILE_BYTES 32768
#define GRID_MAIN 296          // 2 CTAs per SM, all co-resident
#define PREP_CTAS 128
#define NTHREADS 128

// ---------------- device scratch ----------------
__device__ float g_B[HID * HID];                 // Wiv @ Wv
__device__ float g_u[HID];
__device__ __nv_bfloat16 g_Bf[16 * 8 * 2 * 32 * 2]; // 0.5*M^T bf16, fragment layout
__device__ float g_c[HID];
__device__ unsigned int g_tile_ctr;
__device__ unsigned int g_syncA;                 // epoch barrier, 128/epoch
__device__ unsigned int g_syncB;                 // epoch barrier, 296/epoch

__device__ __forceinline__ uint32_t smem_u32(const void* p) {
    uint32_t a;
    asm("{ .reg .u64 t; cvta.to.shared.u64 t, %1; cvt.u32.u64 %0, t; }" : "=r"(a) : "l"(p));
    return a;
}
__device__ __forceinline__ float warp_red(float p) {
    p += __shfl_xor_sync(0xffffffffu, p, 16);
    p += __shfl_xor_sync(0xffffffffu, p, 8);
    p += __shfl_xor_sync(0xffffffffu, p, 4);
    p += __shfl_xor_sync(0xffffffffu, p, 2);
    p += __shfl_xor_sync(0xffffffffu, p, 1);
    return p;
}
__device__ __forceinline__ uint32_t packbf(float lo, float hi) {
    uint32_t d;
    asm("cvt.rn.bf16x2.f32 %0, %1, %2;" : "=r"(d) : "f"(hi), "f"(lo));
    return d;
}
#define CPA16(dst, src) \
    asm volatile("cp.async.cg.shared.global [%0], [%1], 16;" :: "r"(dst), "l"(src))
#define CPA_WAIT_ALL() \
    asm volatile("cp.async.commit_group;\ncp.async.wait_group 0;" ::: "memory")

// smem map (114752 B/CTA): XS0..2 @0/32768/65536, XB @98304 (16KB),
// mbar[3] @114688, sTick[3] @114712
#define OFF_XB   98304u
#define OFF_MBAR 114688u
#define OFF_TICK 114712u
#define SMEM_TOTAL 114752

#define MBAR_INIT(a, c) \
    asm volatile("mbarrier.init.shared.b64 [%0], %1;" :: "r"(a), "r"(c) : "memory")
#define MBAR_EXPECT(a, b) \
    asm volatile("mbarrier.arrive.expect_tx.shared.b64 _, [%0], %1;" :: "r"(a), "r"(b) : "memory")
#define MBAR_WAIT(mbar, par) do {                                             \
    uint32_t _m = (mbar); uint32_t _p = (par); uint32_t _d;                   \
    asm volatile("{\n\t.reg .pred p;\n\t"                                     \
        "mbarrier.try_wait.parity.acquire.cta.shared::cta.b64 p, [%1], %2;\n\t" \
        "selp.b32 %0, 1, 0, p;\n\t}"                                          \
        : "=r"(_d) : "r"(_m), "r"(_p) : "memory");                            \
    if (!_d) {                                                                \
        asm volatile("{\n\t.reg .pred P1;\n\t"                                \
            "W_%=:\n\t"                                                       \
            "mbarrier.try_wait.parity.acquire.cta.shared::cta.b64 P1, [%0], %1, 0x989680;\n\t" \
            "@P1 bra.uni D_%=;\n\t"                                           \
            "bra.uni W_%=;\n\t"                                               \
            "D_%=:\n\t}" :: "r"(_m), "r"(_p) : "memory");                     \
    }                                                                         \
} while (0)

#define TMA_LOAD2D(dst, map, x, y, mb) \
    asm volatile("cp.async.bulk.tensor.2d.shared::cta.global.tile.mbarrier::complete_tx::bytes " \
                 "[%0], [%1, {%2, %3}], [%4];" \
                 :: "r"(dst), "l"(map), "r"(x), "r"(y), "r"(mb) : "memory")
#define TMA_STORE2D(map, x, y, src) \
    asm volatile("cp.async.bulk.tensor.2d.global.shared::cta.tile.bulk_group " \
                 "[%0, {%1, %2}], [%3];" \
                 :: "l"(map), "r"(x), "r"(y), "r"(src) : "memory")
#define FENCE_ASYNC() asm volatile("fence.proxy.async.shared::cta;" ::: "memory")

__global__ __launch_bounds__(NTHREADS, 2) void fused_all(
    const __grid_constant__ CUtensorMap tmX,
    const __grid_constant__ CUtensorMap tmY,
    const float* __restrict__ Wo, const float* __restrict__ W_mo,
    const float* __restrict__ W_in, const float* __restrict__ Wv,
    const float* __restrict__ bv, const float* __restrict__ b_in,
    const float* __restrict__ b_mo, const float* __restrict__ bo,
    int ntiles)
{
    extern __shared__ __align__(1024) unsigned char smem_raw[];
    const uint32_t sb = smem_u32(smem_raw);
    const int tid  = threadIdx.x;
    const int lane = tid & 31, wid = tid >> 5;
    const int wn = wid;                      // 1(m) x 4(n) warp grid
    const int bid = blockIdx.x;
    const uint32_t xs_a[3] = { sb, sb + 32768u, sb + 65536u };
    const uint32_t xb = sb + OFF_XB;
    unsigned* sTick = reinterpret_cast<unsigned*>(smem_raw + OFF_TICK);

    if (tid == 0) {
        #pragma unroll
        for (int st = 0; st < 3; ++st) MBAR_INIT(sb + OFF_MBAR + 8 * st, 1);
    }
    __syncthreads();

    // static prologue tiles for this CTA
    auto issue_prologue = [&]() {
        if (tid == 0) {
            #pragma unroll
            for (int st = 0; st < 3; ++st) {
                const int c = bid + st * GRID_MAIN;
                sTick[st] = (unsigned)c;
                if (c < ntiles) {
                    MBAR_EXPECT(sb + OFF_MBAR + 8 * st, TILE_BYTES);
                    #pragma unroll
                    for (int ac = 0; ac < 4; ++ac)
                        TMA_LOAD2D(xs_a[st] + ac * 8192, &tmX, ac * 32, c * BM,
                                   sb + OFF_MBAR + 8 * st);
                }
            }
        }
    };

    if (bid >= PREP_CTAS) {
        issue_prologue();   // overlaps DRAM with prep compute below
    } else {
        // ===================== prep: fold row r of the weight chain ========
        const int r = bid;
        float* sWf  = reinterpret_cast<float*>(smem_raw);          // 64KB stage
        float* scrf = reinterpret_cast<float*>(smem_raw + OFF_XB); // scratch
        const uint32_t sWa  = sb;
        const uint32_t scra = xb;
        // scratch: sWo @0, sWiv @128, sAsh @256, w_own @384 (floats)

        if (tid < 32) CPA16(scra + tid * 16, Wo + r * HID + tid * 4);
        else if (tid < 64) CPA16(scra + 512 + (tid - 32) * 16,
                                 W_in + (256 + r) * HID + (tid - 32) * 4);
        #pragma unroll
        for (int qq = 0; qq < 32; ++qq) {
            const int i = qq * 128 + tid;
            CPA16(sWa + i * 16, W_mo + i * 4);
        }
        CPA_WAIT_ALL();
        __syncthreads();

        // A[r][tid] = sum_j Wo[r][j] * W_mo[j][tid]
        {
            float a0 = 0.f, a1 = 0.f, a2 = 0.f, a3 = 0.f;
            #pragma unroll
            for (int j = 0; j < HID; j += 4) {
                a0 += scrf[j]     * sWf[j * HID + tid];
                a1 += scrf[j + 1] * sWf[(j + 1) * HID + tid];
                a2 += scrf[j + 2] * sWf[(j + 2) * HID + tid];
                a3 += scrf[j + 3] * sWf[(j + 3) * HID + tid];
            }
            scrf[256 + tid] = (a0 + a1) + (a2 + a3);   // sAsh
        }
        if (wid == 0) {          // u[r]
            float p = 0.f;
            #pragma unroll
            for (int j = lane; j < HID; j += 32) p += scrf[128 + j] * bv[j];
            p = warp_red(p);
            if (lane == 0) g_u[r] = p + b_in[256 + r];
        } else if (wid == 1) {   // w[r]
            float p = 0.f;
            #pragma unroll
            for (int j = lane; j < HID; j += 32) p += scrf[j] * b_mo[j];
            p = warp_red(p);
            if (lane == 0) scrf[384] = p + bo[r];
        }
        __syncthreads();         // done reading W_mo stage

        #pragma unroll
        for (int qq = 0; qq < 32; ++qq) {
            const int i = qq * 128 + tid;
            CPA16(sWa + i * 16, Wv + i * 4);
        }
        CPA_WAIT_ALL();
        __syncthreads();

        // B[r][tid] = sum_j Wiv[r][j] * Wv[j][tid]
        {
            float a0 = 0.f, a1 = 0.f, a2 = 0.f, a3 = 0.f;
            #pragma unroll
            for (int j = 0; j < HID; j += 4) {
                a0 += scrf[128 + j]     * sWf[j * HID + tid];
                a1 += scrf[128 + j + 1] * sWf[(j + 1) * HID + tid];
                a2 += scrf[128 + j + 2] * sWf[(j + 2) * HID + tid];
                a3 += scrf[128 + j + 3] * sWf[(j + 3) * HID + tid];
            }
            g_B[r * HID + tid] = (a0 + a1) + (a2 + a3);
        }
        __threadfence();
        __syncthreads();

        // barrier A: all 128 prep CTAs (epoch, replay-safe)
        if (tid == 0) {
            const unsigned v = atomicAdd(&g_syncA, 1u);
            const unsigned target = ((v >> 7) + 1u) << 7;
            unsigned cur;
            do {
                asm volatile("ld.volatile.global.u32 %0, [%1];" : "=r"(cur) : "l"(&g_syncA));
            } while (cur < target);
        }
        __syncthreads();

        #pragma unroll
        for (int qq = 0; qq < 32; ++qq) {
            const int i = qq * 128 + tid;
            CPA16(sWa + i * 16, g_B + i * 4);
        }
        CPA_WAIT_ALL();
        __syncthreads();

        // M[r][tid] = sum_j A[r][j] * B[j][tid]; scatter bf16 fragment
        {
            float a0 = 0.f, a1 = 0.f, a2 = 0.f, a3 = 0.f;
            #pragma unroll
            for (int j = 0; j < HID; j += 4) {
                a0 += scrf[256 + j]     * sWf[j * HID + tid];
                a1 += scrf[256 + j + 1] * sWf[(j + 1) * HID + tid];
                a2 += scrf[256 + j + 2] * sWf[(j + 2) * HID + tid];
                a3 += scrf[256 + j + 3] * sWf[(j + 3) * HID + tid];
            }
            const float m = 0.5f * ((a0 + a1) + (a2 + a3));
            const int i = tid;
            const int ks = i >> 4, rr = i & 15;
            const int regi = (rr >> 3) & 1, half = rr & 1;
            const int nt = r >> 3;
            const int lane2 = ((r & 7) << 2) | ((rr & 7) >> 1);
            const int idx = ((((nt * 8 + ks) * 2 + regi) * 32) + lane2) * 2 + half;
            g_Bf[idx] = __float2bfloat16(m);
        }
        if (wid == 0) {          // c[r] (needs all g_u -> after barrier A)
            float p = 0.f;
            #pragma unroll
            for (int j = lane; j < HID; j += 32) p += scrf[256 + j] * g_u[j];
            p = warp_red(p);
            if (lane == 0) g_c[r] = 0.5f * (p + scrf[384]);
        }
        __threadfence();
        __syncthreads();

        issue_prologue();        // prep CTA's own tiles, after smem is free
    }

    // ticket counter: seeded past the static prologue tiles (before barrier B)
    if (bid == 0 && tid == 0) {
        g_tile_ctr = 3u * GRID_MAIN;
        __threadfence();
    }

    // barrier B: all 296 CTAs (epoch, replay-safe)
    if (tid == 0) {
        const unsigned v = atomicAdd(&g_syncB, 1u);
        const unsigned target = (v / GRID_MAIN + 1u) * GRID_MAIN;
        unsigned cur;
        do {
            asm volatile("ld.volatile.global.u32 %0, [%1];" : "=r"(cur) : "l"(&g_syncB));
        } while (cur < target);
        __threadfence();
    }
    __syncthreads();

    // ---- B fragments + bias into registers (g_Bf/g_c now published) ----
    uint32_t breg[4][8][2];
    {
        const uint32_t* bp = reinterpret_cast<const uint32_t*>(g_Bf);
        #pragma unroll
        for (int nt = 0; nt < 4; ++nt)
            #pragma unroll
            for (int ks = 0; ks < 8; ++ks)
                #pragma unroll
                for (int ri = 0; ri < 2; ++ri)
                    breg[nt][ks][ri] =
                        bp[(((wn * 4 + nt) * 8 + ks) * 2 + ri) * 32 + lane];
    }
    float cv[4][2];
    #pragma unroll
    for (int nt = 0; nt < 4; ++nt) {
        const int col = wn * 32 + nt * 8 + 2 * (lane & 3);
        cv[nt][0] = g_c[col];
        cv[nt][1] = g_c[col + 1];
    }

    // per-thread constants (R15 mainloop, verbatim)
    const int rsub = lane & 15;
    const uint32_t lr7 = (uint32_t)(rsub & 7);
    const int khalf = lane >> 4;
    const uint32_t rquo = (uint32_t)(lane >> 2);
    const uint32_t c32b = (uint32_t)(2 * (lane & 3));

    unsigned ph = 0;
    int pend_stage = -1;
    unsigned pend_tick = 0;

    for (int i = 0; ; ++i) {
        const int p = i % 3;
        const unsigned q = sTick[p];
        if (q >= (unsigned)ntiles) break;

        MBAR_WAIT(sb + OFF_MBAR + 8 * p, (ph >> p) & 1);
        ph ^= (1u << p);

        float acc[4][4][4];

        // fused: read X (acc ownership), acc = X + c, pack bf16 -> XB
        {
            const uint32_t xsn = xs_a[p] + (uint32_t)wn * 8192;
            #pragma unroll
            for (int mt = 0; mt < 4; ++mt) {
                const uint32_t rA = (uint32_t)(mt * 16) + rquo;
                const uint32_t rB = rA + 8;
                #pragma unroll
                for (int nt = 0; nt < 4; ++nt) {
                    const uint32_t c32 = (uint32_t)(nt * 8) + c32b;
                    const uint32_t cb = c32 * 4;
                    const uint32_t q16 = cb >> 4, inner = cb & 15;
                    const uint32_t aA = xsn + rA * 128 + ((q16 ^ (rA & 7)) << 4) + inner;
                    const uint32_t aB = xsn + rB * 128 + ((q16 ^ (rB & 7)) << 4) + inner;
                    float x0, x1, y0, y1;
                    asm volatile("ld.shared.v2.f32 {%0,%1}, [%2];"
                                 : "=f"(x0), "=f"(x1) : "r"(aA));
                    asm volatile("ld.shared.v2.f32 {%0,%1}, [%2];"
                                 : "=f"(y0), "=f"(y1) : "r"(aB));
                    acc[mt][nt][0] = x0 + cv[nt][0];
                    acc[mt][nt][1] = x1 + cv[nt][1];
                    acc[mt][nt][2] = y0 + cv[nt][0];
                    acc[mt][nt][3] = y1 + cv[nt][1];
                    const uint32_t colb = (uint32_t)(wn * 64) + c32 * 2;
                    const uint32_t qx = colb >> 4, innx = colb & 15;
                    const uint32_t bA = xb + rA * 256 + ((qx ^ (rA & 7)) << 4) + innx;
                    const uint32_t bB = xb + rB * 256 + ((qx ^ (rB & 7)) << 4) + innx;
                    asm volatile("st.shared.b32 [%0], %1;"
                                 :: "r"(bA), "r"(packbf(x0, x1)) : "memory");
                    asm volatile("st.shared.b32 [%0], %1;"
                                 :: "r"(bB), "r"(packbf(y0, y1)) : "memory");
                }
            }
        }
        __syncthreads();

        // mma from XB: warp tile m64 x n32
        #pragma unroll
        for (int ks = 0; ks < 8; ++ks) {
            uint32_t a[4][4];
            const uint32_t chunk = (uint32_t)(2 * ks + khalf);
            const uint32_t csw = (chunk ^ lr7) << 4;
            #pragma unroll
            for (int mt = 0; mt < 4; ++mt) {
                const uint32_t addr = xb + (uint32_t)(mt * 16 + rsub) * 256 + csw;
                asm volatile("ldmatrix.sync.aligned.m8n8.x4.shared.b16 {%0,%1,%2,%3}, [%4];"
                             : "=r"(a[mt][0]), "=r"(a[mt][1]), "=r"(a[mt][2]), "=r"(a[mt][3])
                             : "r"(addr));
            }
            #pragma unroll
            for (int mt = 0; mt < 4; ++mt)
                #pragma unroll
                for (int nt = 0; nt < 4; ++nt) {
                    asm volatile(
                        "mma.sync.aligned.m16n8k16.row.col.f32.bf16.bf16.f32 "
                        "{%0,%1,%2,%3}, {%4,%5,%6,%7}, {%8,%9}, {%0,%1,%2,%3};"
                        : "+f"(acc[mt][nt][0]), "+f"(acc[mt][nt][1]),
                          "+f"(acc[mt][nt][2]), "+f"(acc[mt][nt][3])
                        : "r"(a[mt][0]), "r"(a[mt][1]), "r"(a[mt][2]), "r"(a[mt][3]),
                          "r"(breg[nt][ks][0]), "r"(breg[nt][ks][1]));
                }
        }

        // epilogue: pure STS of acc into XS[p]
        {
            const uint32_t xsn = xs_a[p] + (uint32_t)wn * 8192;
            #pragma unroll
            for (int mt = 0; mt < 4; ++mt) {
                const uint32_t rA = (uint32_t)(mt * 16) + rquo;
                const uint32_t rB = rA + 8;
                #pragma unroll
                for (int nt = 0; nt < 4; ++nt) {
                    const uint32_t c32 = (uint32_t)(nt * 8) + c32b;
                    const uint32_t cb = c32 * 4;
                    const uint32_t q16 = cb >> 4, inner = cb & 15;
                    const uint32_t aA = xsn + rA * 128 + ((q16 ^ (rA & 7)) << 4) + inner;
                    const uint32_t aB = xsn + rB * 128 + ((q16 ^ (rB & 7)) << 4) + inner;
                    asm volatile("st.shared.v2.f32 [%0], {%1,%2};"
                                 :: "r"(aA), "f"(acc[mt][nt][0]), "f"(acc[mt][nt][1]) : "memory");
                    asm volatile("st.shared.v2.f32 [%0], {%1,%2};"
                                 :: "r"(aB), "f"(acc[mt][nt][2]), "f"(acc[mt][nt][3]) : "memory");
                }
            }
        }
        FENCE_ASYNC();
        __syncthreads();

        // tid0: deferred reload, store tile q, new ticket
        if (tid == 0) {
            if (pend_stage >= 0) {
                asm volatile("cp.async.bulk.wait_group.read 0;" ::: "memory");
                if (pend_tick < (unsigned)ntiles) {
                    MBAR_EXPECT(sb + OFF_MBAR + 8 * pend_stage, TILE_BYTES);
                    #pragma unroll
                    for (int ac = 0; ac < 4; ++ac)
                        TMA_LOAD2D(xs_a[pend_stage] + ac * 8192, &tmX,
                                   ac * 32, (int)pend_tick * BM,
                                   sb + OFF_MBAR + 8 * pend_stage);
                }
            }
            #pragma unroll
            for (int ac = 0; ac < 4; ++ac)
                TMA_STORE2D(&tmY, ac * 32, (int)q * BM, xs_a[p] + ac * 8192);
            asm volatile("cp.async.bulk.commit_group;" ::: "memory");
            const unsigned nn = atomicAdd(&g_tile_ctr, 1u);
            sTick[p] = nn;
            pend_tick = nn;
        }
        pend_stage = p;
    }

    if (tid == 0)
        asm volatile("cp.async.bulk.wait_group 0;" ::: "memory");
}

// ================= host ====================================================
typedef CUresult (*PFN_encodeTiled)(
    CUtensorMap*, CUtensorMapDataType, cuuint32_t, void*,
    const cuuint64_t*, const cuuint64_t*, const cuuint32_t*, const cuuint32_t*,
    CUtensorMapInterleave, CUtensorMapSwizzle, CUtensorMapL2promotion,
    CUtensorMapFloatOOBfill);

extern "C" void kernel_launch(void* const* d_in, const int* in_sizes, int n_in,
                              void* d_out, int out_size)
{
    const float* X    = (const float*)d_in[0];
    const float* Wv   = (const float*)d_in[7];
    const float* bv   = (const float*)d_in[8];
    const float* W_in = (const float*)d_in[9];
    const float* b_in = (const float*)d_in[10];
    const float* W_mo = (const float*)d_in[11];
    const float* b_mo = (const float*)d_in[12];
    const float* Wo   = (const float*)d_in[13];
    const float* bo   = (const float*)d_in[14];
    float* Y = (float*)d_out;

    const int E = in_sizes[0] / HID;
    const int ntiles = (E + BM - 1) / BM;

    void* pfn = nullptr;
    cudaDriverEntryPointQueryResult qr;
    cudaGetDriverEntryPoint("cuTensorMapEncodeTiled", &pfn, cudaEnableDefault, &qr);
    PFN_encodeTiled encode = (PFN_encodeTiled)pfn;

    CUtensorMap tmX, tmY;
    cuuint64_t dims[2] = { (cuuint64_t)HID, (cuuint64_t)E };
    cuuint64_t str[1]  = { (cuuint64_t)HID * 4 };
    cuuint32_t box[2]  = { 32, 64 };
    cuuint32_t es[2]   = { 1, 1 };
    encode(&tmX, CU_TENSOR_MAP_DATA_TYPE_FLOAT32, 2, (void*)X,
           dims, str, box, es, CU_TENSOR_MAP_INTERLEAVE_NONE,
           CU_TENSOR_MAP_SWIZZLE_128B, CU_TENSOR_MAP_L2_PROMOTION_L2_128B,
           CU_TENSOR_MAP_FLOAT_OOB_FILL_NONE);
    encode(&tmY, CU_TENSOR_MAP_DATA_TYPE_FLOAT32, 2, (void*)Y,
           dims, str, box, es, CU_TENSOR_MAP_INTERLEAVE_NONE,
           CU_TENSOR_MAP_SWIZZLE_128B, CU_TENSOR_MAP_L2_PROMOTION_L2_128B,
           CU_TENSOR_MAP_FLOAT_OOB_FILL_NONE);

    cudaFuncSetAttribute(fused_all, cudaFuncAttributeMaxDynamicSharedMemorySize, SMEM_TOTAL);
    fused_all<<<GRID_MAIN, NTHREADS, SMEM_TOTAL>>>(
        tmX, tmY, Wo, W_mo, W_in, Wv, bv, b_in, b_mo, bo, ntiles);
}

// round 17
// speedup vs baseline: 1.2766x; 1.0439x over previous
#include <cuda_runtime.h>
#include <cuda.h>
#include <cuda_bf16.h>
#include <cstdint>
#include <cstddef>

#define HID 128
#define BM 64
#define TILE_BYTES 32768
#define GRID_MAIN 296          // 2 CTAs per SM, all co-resident
#define PREP_CTAS 128
#define NTHREADS 128

// ---------------- device scratch ----------------
__device__ __nv_bfloat16 g_Bf[16 * 8 * 2 * 32 * 2]; // 0.5*M^T bf16, fragment layout
__device__ float g_c[HID];
__device__ unsigned int g_tile_ctr;
__device__ unsigned int g_syncB;                 // epoch barrier, 296/epoch

__device__ __forceinline__ uint32_t smem_u32(const void* p) {
    uint32_t a;
    asm("{ .reg .u64 t; cvta.to.shared.u64 t, %1; cvt.u32.u64 %0, t; }" : "=r"(a) : "l"(p));
    return a;
}
__device__ __forceinline__ float warp_red(float p) {
    p += __shfl_xor_sync(0xffffffffu, p, 16);
    p += __shfl_xor_sync(0xffffffffu, p, 8);
    p += __shfl_xor_sync(0xffffffffu, p, 4);
    p += __shfl_xor_sync(0xffffffffu, p, 2);
    p += __shfl_xor_sync(0xffffffffu, p, 1);
    return p;
}
__device__ __forceinline__ uint32_t packbf(float lo, float hi) {
    uint32_t d;
    asm("cvt.rn.bf16x2.f32 %0, %1, %2;" : "=r"(d) : "f"(hi), "f"(lo));
    return d;
}
#define CPA16(dst, src) \
    asm volatile("cp.async.cg.shared.global [%0], [%1], 16;" :: "r"(dst), "l"(src))
#define CPA_WAIT_ALL() \
    asm volatile("cp.async.commit_group;\ncp.async.wait_group 0;" ::: "memory")

// smem map (114752 B/CTA): XS0..2 @0/32768/65536, XB @98304 (16KB),
// mbar[3] @114688, sTick[3] @114712
#define OFF_XB   98304u
#define OFF_MBAR 114688u
#define OFF_TICK 114712u
#define SMEM_TOTAL 114752

#define MBAR_INIT(a, c) \
    asm volatile("mbarrier.init.shared.b64 [%0], %1;" :: "r"(a), "r"(c) : "memory")
#define MBAR_EXPECT(a, b) \
    asm volatile("mbarrier.arrive.expect_tx.shared.b64 _, [%0], %1;" :: "r"(a), "r"(b) : "memory")
#define MBAR_WAIT(mbar, par) do {                                             \
    uint32_t _m = (mbar); uint32_t _p = (par); uint32_t _d;                   \
    asm volatile("{\n\t.reg .pred p;\n\t"                                     \
        "mbarrier.try_wait.parity.acquire.cta.shared::cta.b64 p, [%1], %2;\n\t" \
        "selp.b32 %0, 1, 0, p;\n\t}"                                          \
        : "=r"(_d) : "r"(_m), "r"(_p) : "memory");                            \
    if (!_d) {                                                                \
        asm volatile("{\n\t.reg .pred P1;\n\t"                                \
            "W_%=:\n\t"                                                       \
            "mbarrier.try_wait.parity.acquire.cta.shared::cta.b64 P1, [%0], %1, 0x989680;\n\t" \
            "@P1 bra.uni D_%=;\n\t"                                           \
            "bra.uni W_%=;\n\t"                                               \
            "D_%=:\n\t}" :: "r"(_m), "r"(_p) : "memory");                     \
    }                                                                         \
} while (0)

#define TMA_LOAD2D(dst, map, x, y, mb) \
    asm volatile("cp.async.bulk.tensor.2d.shared::cta.global.tile.mbarrier::complete_tx::bytes " \
                 "[%0], [%1, {%2, %3}], [%4];" \
                 :: "r"(dst), "l"(map), "r"(x), "r"(y), "r"(mb) : "memory")
#define TMA_STORE2D(map, x, y, src) \
    asm volatile("cp.async.bulk.tensor.2d.global.shared::cta.tile.bulk_group " \
                 "[%0, {%1, %2}], [%3];" \
                 :: "l"(map), "r"(x), "r"(y), "r"(src) : "memory")
#define FENCE_ASYNC() asm volatile("fence.proxy.async.shared::cta;" ::: "memory")

__global__ __launch_bounds__(NTHREADS, 2) void fused_all(
    const __grid_constant__ CUtensorMap tmX,
    const __grid_constant__ CUtensorMap tmY,
    const float* __restrict__ Wo, const float* __restrict__ W_mo,
    const float* __restrict__ W_in, const float* __restrict__ Wv,
    const float* __restrict__ bv, const float* __restrict__ b_in,
    const float* __restrict__ b_mo, const float* __restrict__ bo,
    int ntiles)
{
    extern __shared__ __align__(1024) unsigned char smem_raw[];
    const uint32_t sb = smem_u32(smem_raw);
    const int tid  = threadIdx.x;
    const int lane = tid & 31, wid = tid >> 5;
    const int wn = wid;                      // 1(m) x 4(n) warp grid
    const int bid = blockIdx.x;
    const uint32_t xs_a[3] = { sb, sb + 32768u, sb + 65536u };
    const uint32_t xb = sb + OFF_XB;
    unsigned* sTick = reinterpret_cast<unsigned*>(smem_raw + OFF_TICK);

    if (tid == 0) {
        #pragma unroll
        for (int st = 0; st < 3; ++st) MBAR_INIT(sb + OFF_MBAR + 8 * st, 1);
    }
    __syncthreads();

    // static prologue tiles for this CTA
    auto issue_prologue = [&]() {
        if (tid == 0) {
            #pragma unroll
            for (int st = 0; st < 3; ++st) {
                const int c = bid + st * GRID_MAIN;
                sTick[st] = (unsigned)c;
                if (c < ntiles) {
                    MBAR_EXPECT(sb + OFF_MBAR + 8 * st, TILE_BYTES);
                    #pragma unroll
                    for (int ac = 0; ac < 4; ++ac)
                        TMA_LOAD2D(xs_a[st] + ac * 8192, &tmX, ac * 32, c * BM,
                                   sb + OFF_MBAR + 8 * st);
                }
            }
        }
    };

    if (bid >= PREP_CTAS) {
        issue_prologue();   // overlaps DRAM with prep compute below
    } else {
        // ====== prep: row-local chain  row_M = ((Wo[r]@W_mo)@Wiv)@Wv ======
        const int r = bid;
        float* sWf  = reinterpret_cast<float*>(smem_raw);          // 64KB stage
        float* scrf = reinterpret_cast<float*>(smem_raw + OFF_XB); // scratch
        const uint32_t sWa  = sb;
        const uint32_t scra = xb;
        // scratch floats: Wo_r @0, row_A @128, rowAB @256, partials @384

        // stage Wo row + W_mo full
        if (tid < 32) CPA16(scra + tid * 16, Wo + r * HID + tid * 4);
        #pragma unroll
        for (int qq = 0; qq < 32; ++qq) {
            const int i = qq * 128 + tid;
            CPA16(sWa + i * 16, W_mo + i * 4);
        }
        CPA_WAIT_ALL();
        __syncthreads();

        // row_A[t] = sum_j Wo[r][j] * W_mo[j][t]
        {
            float a0 = 0.f, a1 = 0.f, a2 = 0.f, a3 = 0.f;
            #pragma unroll
            for (int j = 0; j < HID; j += 4) {
                a0 += scrf[j]     * sWf[j * HID + tid];
                a1 += scrf[j + 1] * sWf[(j + 1) * HID + tid];
                a2 += scrf[j + 2] * sWf[(j + 2) * HID + tid];
                a3 += scrf[j + 3] * sWf[(j + 3) * HID + tid];
            }
            scrf[128 + tid] = (a0 + a1) + (a2 + a3);
        }
        __syncthreads();

        // stage Wiv full (W_in rows 256..384)
        #pragma unroll
        for (int qq = 0; qq < 32; ++qq) {
            const int i = qq * 128 + tid;
            CPA16(sWa + i * 16, W_in + 256 * HID + i * 4);
        }
        CPA_WAIT_ALL();
        __syncthreads();

        // rowAB[t] = sum_p row_A[p] * Wiv[p][t]
        {
            float a0 = 0.f, a1 = 0.f, a2 = 0.f, a3 = 0.f;
            #pragma unroll
            for (int j = 0; j < HID; j += 4) {
                a0 += scrf[128 + j]     * sWf[j * HID + tid];
                a1 += scrf[128 + j + 1] * sWf[(j + 1) * HID + tid];
                a2 += scrf[128 + j + 2] * sWf[(j + 2) * HID + tid];
                a3 += scrf[128 + j + 3] * sWf[(j + 3) * HID + tid];
            }
            scrf[256 + tid] = (a0 + a1) + (a2 + a3);
        }
        __syncthreads();

        // stage Wv full
        #pragma unroll
        for (int qq = 0; qq < 32; ++qq) {
            const int i = qq * 128 + tid;
            CPA16(sWa + i * 16, Wv + i * 4);
        }
        CPA_WAIT_ALL();
        __syncthreads();

        // row_M[t] = sum_m rowAB[m] * Wv[m][t]; scatter bf16 fragment
        {
            float a0 = 0.f, a1 = 0.f, a2 = 0.f, a3 = 0.f;
            #pragma unroll
            for (int j = 0; j < HID; j += 4) {
                a0 += scrf[256 + j]     * sWf[j * HID + tid];
                a1 += scrf[256 + j + 1] * sWf[(j + 1) * HID + tid];
                a2 += scrf[256 + j + 2] * sWf[(j + 2) * HID + tid];
                a3 += scrf[256 + j + 3] * sWf[(j + 3) * HID + tid];
            }
            const float m = 0.5f * ((a0 + a1) + (a2 + a3));
            const int i = tid;
            const int ks = i >> 4, rr = i & 15;
            const int regi = (rr >> 3) & 1, half = rr & 1;
            const int nt = r >> 3;
            const int lane2 = ((r & 7) << 2) | ((rr & 7) >> 1);
            const int idx = ((((nt * 8 + ks) * 2 + regi) * 32) + lane2) * 2 + half;
            g_Bf[idx] = __float2bfloat16(m);
        }
        // c[r] = 0.5*(rowAB·bv + row_A·biv + Wo[r]·b_mo + bo[r])   (local dots)
        if (wid == 0) {
            float p = 0.f;
            #pragma unroll
            for (int j = lane; j < HID; j += 32) p += scrf[256 + j] * bv[j];
            p = warp_red(p);
            if (lane == 0) scrf[384] = p;
        } else if (wid == 1) {
            float p = 0.f;
            #pragma unroll
            for (int j = lane; j < HID; j += 32) p += scrf[128 + j] * b_in[256 + j];
            p = warp_red(p);
            if (lane == 0) scrf[385] = p;
        } else if (wid == 2) {
            float p = 0.f;
            #pragma unroll
            for (int j = lane; j < HID; j += 32) p += scrf[j] * b_mo[j];
            p = warp_red(p);
            if (lane == 0) scrf[386] = p;
        }
        __syncthreads();
        if (tid == 0)
            g_c[r] = 0.5f * (scrf[384] + scrf[385] + scrf[386] + bo[r]);
        __threadfence();         // publish g_Bf / g_c before barrier B
        __syncthreads();

        issue_prologue();        // prep CTA's own tiles, after smem is free
    }

    // ticket counter: seeded past the static prologue tiles (before barrier B)
    if (bid == 0 && tid == 0) {
        g_tile_ctr = 3u * GRID_MAIN;
        __threadfence();
    }

    // barrier B: all 296 CTAs (epoch, replay-safe)
    if (tid == 0) {
        const unsigned v = atomicAdd(&g_syncB, 1u);
        const unsigned target = (v / GRID_MAIN + 1u) * GRID_MAIN;
        unsigned cur;
        do {
            asm volatile("ld.volatile.global.u32 %0, [%1];" : "=r"(cur) : "l"(&g_syncB));
        } while (cur < target);
        __threadfence();
    }
    __syncthreads();

    // ---- B fragments + bias into registers (g_Bf/g_c now published) ----
    uint32_t breg[4][8][2];
    {
        const uint32_t* bp = reinterpret_cast<const uint32_t*>(g_Bf);
        #pragma unroll
        for (int nt = 0; nt < 4; ++nt)
            #pragma unroll
            for (int ks = 0; ks < 8; ++ks)
                #pragma unroll
                for (int ri = 0; ri < 2; ++ri)
                    breg[nt][ks][ri] =
                        bp[(((wn * 4 + nt) * 8 + ks) * 2 + ri) * 32 + lane];
    }
    float cv[4][2];
    #pragma unroll
    for (int nt = 0; nt < 4; ++nt) {
        const int col = wn * 32 + nt * 8 + 2 * (lane & 3);
        cv[nt][0] = g_c[col];
        cv[nt][1] = g_c[col + 1];
    }

    // per-thread constants (R15/R16 mainloop, verbatim)
    const int rsub = lane & 15;
    const uint32_t lr7 = (uint32_t)(rsub & 7);
    const int khalf = lane >> 4;
    const uint32_t rquo = (uint32_t)(lane >> 2);
    const uint32_t c32b = (uint32_t)(2 * (lane & 3));

    unsigned ph = 0;
    int pend_stage = -1;
    unsigned pend_tick = 0;

    for (int i = 0; ; ++i) {
        const int p = i % 3;
        const unsigned q = sTick[p];
        if (q >= (unsigned)ntiles) break;

        MBAR_WAIT(sb + OFF_MBAR + 8 * p, (ph >> p) & 1);
        ph ^= (1u << p);

        float acc[4][4][4];

        // fused: read X (acc ownership), acc = X + c, pack bf16 -> XB
        {
            const uint32_t xsn = xs_a[p] + (uint32_t)wn * 8192;
            #pragma unroll
            for (int mt = 0; mt < 4; ++mt) {
                const uint32_t rA = (uint32_t)(mt * 16) + rquo;
                const uint32_t rB = rA + 8;
                #pragma unroll
                for (int nt = 0; nt < 4; ++nt) {
                    const uint32_t c32 = (uint32_t)(nt * 8) + c32b;
                    const uint32_t cb = c32 * 4;
                    const uint32_t q16 = cb >> 4, inner = cb & 15;
                    const uint32_t aA = xsn + rA * 128 + ((q16 ^ (rA & 7)) << 4) + inner;
                    const uint32_t aB = xsn + rB * 128 + ((q16 ^ (rB & 7)) << 4) + inner;
                    float x0, x1, y0, y1;
                    asm volatile("ld.shared.v2.f32 {%0,%1}, [%2];"
                                 : "=f"(x0), "=f"(x1) : "r"(aA));
                    asm volatile("ld.shared.v2.f32 {%0,%1}, [%2];"
                                 : "=f"(y0), "=f"(y1) : "r"(aB));
                    acc[mt][nt][0] = x0 + cv[nt][0];
                    acc[mt][nt][1] = x1 + cv[nt][1];
                    acc[mt][nt][2] = y0 + cv[nt][0];
                    acc[mt][nt][3] = y1 + cv[nt][1];
                    const uint32_t colb = (uint32_t)(wn * 64) + c32 * 2;
                    const uint32_t qx = colb >> 4, innx = colb & 15;
                    const uint32_t bA = xb + rA * 256 + ((qx ^ (rA & 7)) << 4) + innx;
                    const uint32_t bB = xb + rB * 256 + ((qx ^ (rB & 7)) << 4) + innx;
                    asm volatile("st.shared.b32 [%0], %1;"
                                 :: "r"(bA), "r"(packbf(x0, x1)) : "memory");
                    asm volatile("st.shared.b32 [%0], %1;"
                                 :: "r"(bB), "r"(packbf(y0, y1)) : "memory");
                }
            }
        }
        __syncthreads();

        // mma from XB: warp tile m64 x n32
        #pragma unroll
        for (int ks = 0; ks < 8; ++ks) {
            uint32_t a[4][4];
            const uint32_t chunk = (uint32_t)(2 * ks + khalf);
            const uint32_t csw = (chunk ^ lr7) << 4;
            #pragma unroll
            for (int mt = 0; mt < 4; ++mt) {
                const uint32_t addr = xb + (uint32_t)(mt * 16 + rsub) * 256 + csw;
                asm volatile("ldmatrix.sync.aligned.m8n8.x4.shared.b16 {%0,%1,%2,%3}, [%4];"
                             : "=r"(a[mt][0]), "=r"(a[mt][1]), "=r"(a[mt][2]), "=r"(a[mt][3])
                             : "r"(addr));
            }
            #pragma unroll
            for (int mt = 0; mt < 4; ++mt)
                #pragma unroll
                for (int nt = 0; nt < 4; ++nt) {
                    asm volatile(
                        "mma.sync.aligned.m16n8k16.row.col.f32.bf16.bf16.f32 "
                        "{%0,%1,%2,%3}, {%4,%5,%6,%7}, {%8,%9}, {%0,%1,%2,%3};"
                        : "+f"(acc[mt][nt][0]), "+f"(acc[mt][nt][1]),
                          "+f"(acc[mt][nt][2]), "+f"(acc[mt][nt][3])
                        : "r"(a[mt][0]), "r"(a[mt][1]), "r"(a[mt][2]), "r"(a[mt][3]),
                          "r"(breg[nt][ks][0]), "r"(breg[nt][ks][1]));
                }
        }

        // epilogue: pure STS of acc into XS[p]
        {
            const uint32_t xsn = xs_a[p] + (uint32_t)wn * 8192;
            #pragma unroll
            for (int mt = 0; mt < 4; ++mt) {
                const uint32_t rA = (uint32_t)(mt * 16) + rquo;
                const uint32_t rB = rA + 8;
                #pragma unroll
                for (int nt = 0; nt < 4; ++nt) {
                    const uint32_t c32 = (uint32_t)(nt * 8) + c32b;
                    const uint32_t cb = c32 * 4;
                    const uint32_t q16 = cb >> 4, inner = cb & 15;
                    const uint32_t aA = xsn + rA * 128 + ((q16 ^ (rA & 7)) << 4) + inner;
                    const uint32_t aB = xsn + rB * 128 + ((q16 ^ (rB & 7)) << 4) + inner;
                    asm volatile("st.shared.v2.f32 [%0], {%1,%2};"
                                 :: "r"(aA), "f"(acc[mt][nt][0]), "f"(acc[mt][nt][1]) : "memory");
                    asm volatile("st.shared.v2.f32 [%0], {%1,%2};"
                                 :: "r"(aB), "f"(acc[mt][nt][2]), "f"(acc[mt][nt][3]) : "memory");
                }
            }
        }
        FENCE_ASYNC();
        __syncthreads();

        // tid0: deferred reload, store tile q, new ticket
        if (tid == 0) {
            if (pend_stage >= 0) {
                asm volatile("cp.async.bulk.wait_group.read 0;" ::: "memory");
                if (pend_tick < (unsigned)ntiles) {
                    MBAR_EXPECT(sb + OFF_MBAR + 8 * pend_stage, TILE_BYTES);
                    #pragma unroll
                    for (int ac = 0; ac < 4; ++ac)
                        TMA_LOAD2D(xs_a[pend_stage] + ac * 8192, &tmX,
                                   ac * 32, (int)pend_tick * BM,
                                   sb + OFF_MBAR + 8 * pend_stage);
                }
            }
            #pragma unroll
            for (int ac = 0; ac < 4; ++ac)
                TMA_STORE2D(&tmY, ac * 32, (int)q * BM, xs_a[p] + ac * 8192);
            asm volatile("cp.async.bulk.commit_group;" ::: "memory");
            const unsigned nn = atomicAdd(&g_tile_ctr, 1u);
            sTick[p] = nn;
            pend_tick = nn;
        }
        pend_stage = p;
    }

    if (tid == 0)
        asm volatile("cp.async.bulk.wait_group 0;" ::: "memory");
}

// ================= host ====================================================
typedef CUresult (*PFN_encodeTiled)(
    CUtensorMap*, CUtensorMapDataType, cuuint32_t, void*,
    const cuuint64_t*, const cuuint64_t*, const cuuint32_t*, const cuuint32_t*,
    CUtensorMapInterleave, CUtensorMapSwizzle, CUtensorMapL2promotion,
    CUtensorMapFloatOOBfill);

extern "C" void kernel_launch(void* const* d_in, const int* in_sizes, int n_in,
                              void* d_out, int out_size)
{
    const float* X    = (const float*)d_in[0];
    const float* Wv   = (const float*)d_in[7];
    const float* bv   = (const float*)d_in[8];
    const float* W_in = (const float*)d_in[9];
    const float* b_in = (const float*)d_in[10];
    const float* W_mo = (const float*)d_in[11];
    const float* b_mo = (const float*)d_in[12];
    const float* Wo   = (const float*)d_in[13];
    const float* bo   = (const float*)d_in[14];
    float* Y = (float*)d_out;

    const int E = in_sizes[0] / HID;
    const int ntiles = (E + BM - 1) / BM;

    void* pfn = nullptr;
    cudaDriverEntryPointQueryResult qr;
    cudaGetDriverEntryPoint("cuTensorMapEncodeTiled", &pfn, cudaEnableDefault, &qr);
    PFN_encodeTiled encode = (PFN_encodeTiled)pfn;

    CUtensorMap tmX, tmY;
    cuuint64_t dims[2] = { (cuuint64_t)HID, (cuuint64_t)E };
    cuuint64_t str[1]  = { (cuuint64_t)HID * 4 };
    cuuint32_t box[2]  = { 32, 64 };
    cuuint32_t es[2]   = { 1, 1 };
    encode(&tmX, CU_TENSOR_MAP_DATA_TYPE_FLOAT32, 2, (void*)X,
           dims, str, box, es, CU_TENSOR_MAP_INTERLEAVE_NONE,
           CU_TENSOR_MAP_SWIZZLE_128B, CU_TENSOR_MAP_L2_PROMOTION_L2_128B,
           CU_TENSOR_MAP_FLOAT_OOB_FILL_NONE);
    encode(&tmY, CU_TENSOR_MAP_DATA_TYPE_FLOAT32, 2, (void*)Y,
           dims, str, box, es, CU_TENSOR_MAP_INTERLEAVE_NONE,
           CU_TENSOR_MAP_SWIZZLE_128B, CU_TENSOR_MAP_L2_PROMOTION_L2_128B,
           CU_TENSOR_MAP_FLOAT_OOB_FILL_NONE);

    cudaFuncSetAttribute(fused_all, cudaFuncAttributeMaxDynamicSharedMemorySize, SMEM_TOTAL);
    fused_all<<<GRID_MAIN, NTHREADS, SMEM_TOTAL>>>(
        tmX, tmY, Wo, W_mo, W_in, Wv, bv, b_in, b_mo, bo, ntiles);
}